// round 12
// baseline (speedup 1.0000x reference)
#include <cuda_runtime.h>

// ---------------- problem constants ----------------
#define Bq   8
#define Np   16384
#define Sq   2048
#define Kq   32
#define CIN  64
#define C0   67      // 3 + CIN
#define C3   128
#define PTOT (Bq*Sq*Kq)   // 524288
#define EPSV 1e-5f

// ---------------- device scratch (no allocs allowed) ----------------
__device__ int   g_fps_idx[Bq*Sq];
__device__ int   g_knn_idx[PTOT];
__device__ float g_pointsT[(long)Bq*Np*CIN];   // points transposed: [b][n][c]
__device__ float g_feats[(long)PTOT*C0];       // [p][i]
__device__ float g_x0[(long)PTOT*64];          // raw conv0 out
__device__ float g_x1[(long)PTOT*64];          // raw conv1 out
__device__ float g_x2[(long)PTOT*128];         // raw conv2 out
__device__ float g_stats[256];                 // [0..127] sum, [128..255] sumsq
__device__ float g_scale[128];
__device__ float g_shift[128];
__device__ unsigned int       g_cnt[Bq];
__device__ unsigned long long g_part[Bq][2][16];

// ---------------- init ----------------
__global__ void k_zero() {
    int t = threadIdx.x;
    if (t < 256) g_stats[t] = 0.f;
    if (t < Bq)  g_cnt[t] = 0u;
}

// ---------------- FPS: 16 CTAs per batch, spin-synced ----------------
__device__ __forceinline__ unsigned long long pk_max(unsigned long long a, unsigned long long b) {
    return a > b ? a : b;
}

__global__ void __launch_bounds__(256) k_fps(const float* __restrict__ xyz,
                                             float* __restrict__ out) {
    int j   = blockIdx.x;          // block within batch: 0..15
    int b   = blockIdx.y;
    int tid = threadIdx.x;
    const float* xb = xyz + b*3*Np;
    int base = j * 1024;

    float px[4], py[4], pz[4], dist[4];
#pragma unroll
    for (int i = 0; i < 4; i++) {
        int n = base + i*256 + tid;
        px[i] = xb[n]; py[i] = xb[Np + n]; pz[i] = xb[2*Np + n];
        dist[i] = 1e10f;
    }

    __shared__ unsigned long long s_w[8];
    __shared__ float s_cx, s_cy, s_cz;
    __shared__ int   s_ci;

    int   cur = 0;
    float cx = xb[0], cy = xb[Np], cz = xb[2*Np];
    volatile unsigned int* cnt = &g_cnt[b];

    for (int s = 0; s < Sq; s++) {
        if (j == 0 && tid == 0) {
            g_fps_idx[b*Sq + s] = cur;
            out[b*3*Sq + s]          = cx;
            out[b*3*Sq + Sq + s]     = cy;
            out[b*3*Sq + 2*Sq + s]   = cz;
        }
        if (s == Sq - 1) break;

        // update distances + local packed argmax (max dist, min index on ties)
        unsigned long long best = 0ull;
#pragma unroll
        for (int i = 0; i < 4; i++) {
            float dx = px[i] - cx, dy = py[i] - cy, dz = pz[i] - cz;
            float d  = dx*dx + dy*dy + dz*dz;
            float nd = fminf(dist[i], d);
            dist[i] = nd;
            int n = base + i*256 + tid;
            unsigned long long pk =
                ((unsigned long long)__float_as_uint(nd) << 32) |
                (unsigned int)(0xFFFFFFFFu - (unsigned)n);
            best = pk_max(best, pk);
        }
#pragma unroll
        for (int o = 16; o; o >>= 1)
            best = pk_max(best, __shfl_down_sync(0xffffffffu, best, o));

        int wid = tid >> 5, lane = tid & 31;
        if (lane == 0) s_w[wid] = best;
        __syncthreads();

        if (wid == 0) {
            best = (lane < 8) ? s_w[lane] : 0ull;
#pragma unroll
            for (int o = 4; o; o >>= 1)
                best = pk_max(best, __shfl_down_sync(0xffffffffu, best, o));

            int par = s & 1;
            if (lane == 0) {
                ((volatile unsigned long long*)&g_part[b][par][0])[j] = best;
                __threadfence();
                atomicAdd(&g_cnt[b], 1u);
            }
            unsigned int target = 16u * (unsigned)(s + 1);
            while (*cnt < target) { }

            unsigned long long pk =
                (lane < 16) ? ((volatile unsigned long long*)&g_part[b][par][0])[lane] : 0ull;
#pragma unroll
            for (int o = 8; o; o >>= 1)
                pk = pk_max(pk, __shfl_down_sync(0xffffffffu, pk, o));
            if (lane == 0) {
                int w = (int)(0xFFFFFFFFu - (unsigned int)(pk & 0xFFFFFFFFull));
                s_ci = w;
                s_cx = xb[w]; s_cy = xb[Np + w]; s_cz = xb[2*Np + w];
            }
        }
        __syncthreads();
        cur = s_ci; cx = s_cx; cy = s_cy; cz = s_cz;
    }
}

// ---------------- kNN: thread per query, insertion top-K ----------------
__global__ void __launch_bounds__(128) k_knn(const float* __restrict__ xyz) {
    int b = blockIdx.y;
    int s = blockIdx.x * 128 + threadIdx.x;
    const float* xb = xyz + b*3*Np;
    int qn = g_fps_idx[b*Sq + s];
    float qx = xb[qn], qy = xb[Np + qn], qz = xb[2*Np + qn];
    float q2 = qx*qx + qy*qy + qz*qz;

    float bd[Kq]; int bi[Kq];
#pragma unroll
    for (int k = 0; k < Kq; k++) { bd[k] = 3.0e38f; bi[k] = 0; }
    float worst = 3.0e38f;

    __shared__ float4 sp[512];
    for (int n0 = 0; n0 < Np; n0 += 512) {
        __syncthreads();
        for (int t = threadIdx.x; t < 512; t += 128) {
            float x = xb[n0 + t], y = xb[Np + n0 + t], z = xb[2*Np + n0 + t];
            sp[t] = make_float4(x, y, z, x*x + y*y + z*z);
        }
        __syncthreads();
#pragma unroll 4
        for (int t = 0; t < 512; t++) {
            float4 p = sp[t];
            float d = (q2 + p.w) - 2.0f * (qx*p.x + qy*p.y + qz*p.z);
            if (d < worst) {
                int pos = Kq - 1;
                while (pos > 0 && bd[pos-1] > d) {
                    bd[pos] = bd[pos-1]; bi[pos] = bi[pos-1]; pos--;
                }
                bd[pos] = d; bi[pos] = n0 + t;
                worst = bd[Kq-1];
            }
        }
    }
    int o = (b*Sq + s) * Kq;
    for (int k = 0; k < Kq; k++) g_knn_idx[o + k] = bi[k];
}

// ---------------- transpose points (B,C,N) -> (B,N,C) ----------------
__global__ void k_transpose(const float* __restrict__ pts) {
    __shared__ float tile[32][33];
    int b  = blockIdx.z;
    int n0 = blockIdx.x * 32, c0 = blockIdx.y * 32;
    int x = threadIdx.x, y = threadIdx.y;
    for (int r = y; r < 32; r += 8)
        tile[r][x] = pts[(long)b*CIN*Np + (c0 + r)*Np + n0 + x];
    __syncthreads();
    for (int r = y; r < 32; r += 8)
        g_pointsT[((long)b*Np + (n0 + r)) * CIN + c0 + x] = tile[x][r];
}

// ---------------- gather + concat -> feats [p][67] ----------------
__global__ void k_gather(const float* __restrict__ xyz) {
    long t = (long)blockIdx.x * blockDim.x + threadIdx.x;
    if (t >= (long)PTOT * C0) return;
    int p = (int)(t / C0);
    int i = (int)(t - (long)p * C0);
    int b = p >> 16;                 // / (Sq*Kq)
    int s = (p >> 5) & (Sq - 1);
    int n = g_knn_idx[p];
    float v;
    if (i < 3) {
        const float* xb = xyz + b*3*Np;
        int q = g_fps_idx[b*Sq + s];
        v = xb[i*Np + n] - xb[i*Np + q];
    } else {
        v = g_pointsT[((long)b*Np + n) * CIN + (i - 3)];
    }
    g_feats[t] = v;
}

// ---------------- conv (GEMM): out[p][co] = sum_i act(in[p][i]) * W[co][i] ----
template<int LAYER>
__global__ void __launch_bounds__(256) k_conv(const float* __restrict__ W) {
    constexpr int CI = (LAYER == 0) ? 67 : 64;
    constexpr int CO = (LAYER == 2) ? 128 : 64;
    constexpr bool BN = (LAYER != 0);
    constexpr int TN = CO / 16;
    const float* A = (LAYER == 0) ? g_feats : ((LAYER == 1) ? g_x0 : g_x1);
    float*       O = (LAYER == 0) ? g_x0   : ((LAYER == 1) ? g_x1 : g_x2);

    __shared__ __align__(16) float sA[16][68];
    __shared__ float sB[CO][17];
    __shared__ float sS[68], sH[68];

    int tid = threadIdx.x;
    int m0  = blockIdx.x * 64;
    int tx = tid & 15, ty = tid >> 4;

    if (BN) {
        if (tid < CI) { sS[tid] = g_scale[tid]; sH[tid] = g_shift[tid]; }
    }

    float acc[4][TN];
#pragma unroll
    for (int i = 0; i < 4; i++)
#pragma unroll
        for (int jj = 0; jj < TN; jj++) acc[i][jj] = 0.f;

    const int KCH = (CI + 15) / 16;
    for (int kc = 0; kc < KCH; kc++) {
        int k0 = kc * 16;
        __syncthreads();
        // A tile: 64 points x 16 channels (+ fused BN/ReLU of previous layer)
#pragma unroll
        for (int r = 0; r < 4; r++) {
            int e = tid + 256 * r;
            int m = e >> 4, kk = e & 15;
            int col = k0 + kk;
            float v = 0.f;
            if (col < CI) {
                v = A[(m0 + m) * CI + col];
                if (BN) v = fmaxf(v * sS[col] + sH[col], 0.f);
            }
            sA[kk][m] = v;
        }
        // B tile: CO x 16
#pragma unroll
        for (int r = 0; r < (CO * 16) / 256; r++) {
            int e = tid + 256 * r;
            int co = e >> 4, kk = e & 15;
            int col = k0 + kk;
            sB[co][kk] = (col < CI) ? W[co * CI + col] : 0.f;
        }
        __syncthreads();
#pragma unroll
        for (int kk = 0; kk < 16; kk++) {
            float4 a4 = *(const float4*)&sA[kk][ty * 4];
            float a[4] = {a4.x, a4.y, a4.z, a4.w};
            float bb[TN];
#pragma unroll
            for (int jj = 0; jj < TN; jj++) bb[jj] = sB[tx * TN + jj][kk];
#pragma unroll
            for (int i = 0; i < 4; i++)
#pragma unroll
                for (int jj = 0; jj < TN; jj++)
                    acc[i][jj] += a[i] * bb[jj];
        }
    }
#pragma unroll
    for (int i = 0; i < 4; i++) {
        int row = m0 + ty * 4 + i;
#pragma unroll
        for (int jj = 0; jj < TN; jj += 4) {
            float4 v = make_float4(acc[i][jj], acc[i][jj+1], acc[i][jj+2], acc[i][jj+3]);
            *(float4*)&O[row * CO + tx * TN + jj] = v;
        }
    }
}

// ---------------- per-channel BN stats (sum, sumsq) ----------------
template<int LAYER>
__global__ void k_stats() {
    constexpr int CO = (LAYER == 2) ? 128 : 64;
    const float* X = (LAYER == 0) ? g_x0 : ((LAYER == 1) ? g_x1 : g_x2);
    int co = threadIdx.x & (CO - 1);
    int rr = threadIdx.x / CO;
    const int RPB = 256 / CO;
    float s = 0.f, s2 = 0.f;
    for (int r = blockIdx.x * RPB + rr; r < PTOT; r += gridDim.x * RPB) {
        float v = X[r * CO + co];
        s += v; s2 = fmaf(v, v, s2);
    }
    atomicAdd(&g_stats[co], s);
    atomicAdd(&g_stats[128 + co], s2);
}

__global__ void k_bnfin(const float* __restrict__ g, const float* __restrict__ bb, int CO) {
    int c = threadIdx.x;
    if (c < CO) {
        const float inv = 1.0f / (float)PTOT;
        float mean = g_stats[c] * inv;
        float var  = fmaxf(g_stats[128 + c] * inv - mean * mean, 0.f);
        float sc   = g[c] / sqrtf(var + EPSV);
        g_scale[c] = sc;
        g_shift[c] = bb[c] - mean * sc;
    }
}

// ---------------- BN2 + ReLU + maxpool over K -> new_points ----------------
__global__ void __launch_bounds__(128) k_maxpool(float* __restrict__ out) {
    int bs = blockIdx.x;          // b*Sq + s
    int c  = threadIdx.x;         // 0..127
    int b = bs >> 11, s = bs & (Sq - 1);
    const float* xp = g_x2 + (long)bs * Kq * C3;
    float sc = g_scale[c], sh = g_shift[c];
    float m = 0.f;                // ReLU outputs are >= 0
#pragma unroll 8
    for (int k = 0; k < Kq; k++) {
        float v = xp[k * C3 + c];
        m = fmaxf(m, fmaxf(v * sc + sh, 0.f));
    }
    out[Bq*3*Sq + b*C3*Sq + c*Sq + s] = m;
}

// ---------------- launch ----------------
extern "C" void kernel_launch(void* const* d_in, const int* in_sizes, int n_in,
                              void* d_out, int out_size) {
    const float* xyz    = (const float*)d_in[0];
    const float* points = (const float*)d_in[1];
    const float* W0 = (const float*)d_in[2];
    const float* g0 = (const float*)d_in[3];
    const float* b0 = (const float*)d_in[4];
    const float* W1 = (const float*)d_in[5];
    const float* g1 = (const float*)d_in[6];
    const float* b1 = (const float*)d_in[7];
    const float* W2 = (const float*)d_in[8];
    const float* g2 = (const float*)d_in[9];
    const float* b2 = (const float*)d_in[10];
    float* out = (float*)d_out;

    k_zero<<<1, 256>>>();
    k_fps<<<dim3(16, Bq), 256>>>(xyz, out);
    k_knn<<<dim3(Sq/128, Bq), 128>>>(xyz);
    k_transpose<<<dim3(Np/32, CIN/32, Bq), dim3(32, 8)>>>(points);
    {
        long tot = (long)PTOT * C0;
        k_gather<<<(unsigned)((tot + 255) / 256), 256>>>(xyz);
    }
    k_conv<0><<<PTOT/64, 256>>>(W0);
    k_stats<0><<<1024, 256>>>();
    k_bnfin<<<1, 128>>>(g0, b0, 64);

    k_zero<<<1, 256>>>();
    k_conv<1><<<PTOT/64, 256>>>(W1);
    k_stats<1><<<1024, 256>>>();
    k_bnfin<<<1, 128>>>(g1, b1, 64);

    k_zero<<<1, 256>>>();
    k_conv<2><<<PTOT/64, 256>>>(W2);
    k_stats<2><<<1024, 256>>>();
    k_bnfin<<<1, 128>>>(g2, b2, 128);

    k_maxpool<<<Bq*Sq, 128>>>(out);
}